// round 1
// baseline (speedup 1.0000x reference)
#include <cuda_runtime.h>
#include <math.h>
#include <float.h>

#define NN 50000
#define NE 800000
#define D 128
#define PITCH 132   // smem pitch in floats (multiple of 4, avoids worst bank patterns)

// ---------------- scratch (static device globals: allocation-free) ----------------
__device__ float g_S[NN * D];       // feat @ (W_asrc+W_asub)^T
__device__ float g_Dt[NN * D];      // feat @ (W_adst-W_asub)^T
__device__ float g_H[NN * D];       // gelu(feat@W_pool^T + b_pool)
__device__ float g_H2[NN * D];      // gelu(feat@W_pool2^T + b_pool2)
__device__ float g_neigh[NN * D];
__device__ float g_neigh2[NN * D];
__device__ int   g_deg[NN];
__device__ int   g_rowptr[NN + 1];
__device__ int   g_cursor[NN];
__device__ int   g_sbuf[NE];        // src node id at sorted (CSR) position
__device__ int   g_pos[NE];         // edge e -> CSR position
__device__ float g_score[NE];       // attention score at sorted position
__device__ float g_WS[D * D];
__device__ float g_WD[D * D];
__device__ float g_be[D];           // combined bias for e

__device__ __forceinline__ float gelu_f(float x) {
    return 0.5f * x * (1.0f + erff(x * 0.70710678118654752f));
}

// ---------------- tiny prep kernels ----------------
__global__ void prep_kernel(const float* __restrict__ Wasrc, const float* __restrict__ Wadst,
                            const float* __restrict__ Wasub,
                            const float* __restrict__ basrc, const float* __restrict__ badst,
                            const float* __restrict__ basub, const float* __restrict__ bamul) {
    int i = blockIdx.x * blockDim.x + threadIdx.x;
    if (i < D * D) {
        g_WS[i] = Wasrc[i] + Wasub[i];
        g_WD[i] = Wadst[i] - Wasub[i];
    }
    if (i < D) g_be[i] = basrc[i] + badst[i] + basub[i] + bamul[i];
}

__global__ void init_deg_kernel() {
    int i = blockIdx.x * blockDim.x + threadIdx.x;
    if (i < NN) g_deg[i] = 0;
}

__global__ void deg_kernel(const int* __restrict__ dst) {
    int e = blockIdx.x * blockDim.x + threadIdx.x;
    if (e < NE) atomicAdd(&g_deg[dst[e]], 1);
}

// single-block exclusive scan over 50000 degrees -> rowptr, cursor
__global__ void scan_kernel() {
    __shared__ int part[1024];
    int t = threadIdx.x;
    const int CH = (NN + 1023) / 1024;
    int start = t * CH;
    int s = 0;
    for (int i = 0; i < CH; i++) {
        int idx = start + i;
        if (idx < NN) s += g_deg[idx];
    }
    part[t] = s;
    __syncthreads();
    for (int off = 1; off < 1024; off <<= 1) {
        int v = (t >= off) ? part[t - off] : 0;
        __syncthreads();
        part[t] += v;
        __syncthreads();
    }
    int base = (t == 0) ? 0 : part[t - 1];
    for (int i = 0; i < CH; i++) {
        int idx = start + i;
        if (idx < NN) {
            g_rowptr[idx] = base;
            g_cursor[idx] = base;
            base += g_deg[idx];
        }
    }
    if (t == 1023) g_rowptr[NN] = part[1023];
}

__global__ void fill_kernel(const int* __restrict__ src, const int* __restrict__ dst) {
    int e = blockIdx.x * blockDim.x + threadIdx.x;
    if (e < NE) {
        int p = atomicAdd(&g_cursor[dst[e]], 1);
        g_sbuf[p] = src[e];
        g_pos[e] = p;
    }
}

// ---------------- stage 1: node GEMMs (S, Dt, H, H2) ----------------
__global__ __launch_bounds__(256, 1) void node1_kernel(
    const float* __restrict__ feat,
    const float* __restrict__ Wpool, const float* __restrict__ bpool,
    const float* __restrict__ Wpool2, const float* __restrict__ bpool2) {
    extern __shared__ float sm[];
    float* As = sm;               // [k][m] 128 x PITCH
    float* Bs = sm + D * PITCH;   // [k][j]
    __shared__ float sbias[D];
    int t = threadIdx.x;
    int base = blockIdx.x * 128;

    {   // load A tile transposed
        int m = t >> 1, k0 = (t & 1) * 64;
        int node = base + m;
        if (node < NN) {
            const float* row = &feat[(size_t)node * D];
#pragma unroll
            for (int k = k0; k < k0 + 64; k += 4) {
                float4 v = *(const float4*)&row[k];
                As[(k + 0) * PITCH + m] = v.x;
                As[(k + 1) * PITCH + m] = v.y;
                As[(k + 2) * PITCH + m] = v.z;
                As[(k + 3) * PITCH + m] = v.w;
            }
        } else {
            for (int k = k0; k < k0 + 64; k++) As[k * PITCH + m] = 0.f;
        }
    }
    int ty = t >> 4, tx = t & 15, m0 = ty * 8, j0 = tx * 8;

    for (int mat = 0; mat < 4; mat++) {
        const float* W = (mat == 0) ? g_WS : (mat == 1) ? g_WD : (mat == 2) ? Wpool : Wpool2;
        __syncthreads();
        {
            int j = t >> 1, k0 = (t & 1) * 64;
            const float* wr = &W[j * D];
#pragma unroll
            for (int k = k0; k < k0 + 64; k += 4) {
                float4 v = *(const float4*)&wr[k];
                Bs[(k + 0) * PITCH + j] = v.x;
                Bs[(k + 1) * PITCH + j] = v.y;
                Bs[(k + 2) * PITCH + j] = v.z;
                Bs[(k + 3) * PITCH + j] = v.w;
            }
            if (t < D) sbias[t] = (mat == 2) ? bpool[t] : (mat == 3) ? bpool2[t] : 0.f;
        }
        __syncthreads();

        float acc[8][8];
#pragma unroll
        for (int i = 0; i < 8; i++)
#pragma unroll
            for (int j = 0; j < 8; j++) acc[i][j] = 0.f;

#pragma unroll 4
        for (int k = 0; k < D; k++) {
            float4 a0 = *(float4*)&As[k * PITCH + m0];
            float4 a1 = *(float4*)&As[k * PITCH + m0 + 4];
            float4 b0 = *(float4*)&Bs[k * PITCH + j0];
            float4 b1 = *(float4*)&Bs[k * PITCH + j0 + 4];
            float a[8] = {a0.x, a0.y, a0.z, a0.w, a1.x, a1.y, a1.z, a1.w};
            float b[8] = {b0.x, b0.y, b0.z, b0.w, b1.x, b1.y, b1.z, b1.w};
#pragma unroll
            for (int i = 0; i < 8; i++)
#pragma unroll
                for (int j = 0; j < 8; j++) acc[i][j] = fmaf(a[i], b[j], acc[i][j]);
        }

        float* OUT = (mat == 0) ? g_S : (mat == 1) ? g_Dt : (mat == 2) ? g_H : g_H2;
#pragma unroll
        for (int i = 0; i < 8; i++) {
            int node = base + m0 + i;
            if (node >= NN) break;
            float o[8];
#pragma unroll
            for (int j = 0; j < 8; j++) {
                float v = acc[i][j];
                if (mat >= 2) v = gelu_f(v + sbias[j0 + j]);
                o[j] = v;
            }
            *(float4*)&OUT[(size_t)node * D + j0] = make_float4(o[0], o[1], o[2], o[3]);
            *(float4*)&OUT[(size_t)node * D + j0 + 4] = make_float4(o[4], o[5], o[6], o[7]);
        }
    }
}

// ---------------- stage 2: edge attention scores ----------------
__global__ __launch_bounds__(256, 1) void edge_kernel(
    const float* __restrict__ feat, const int* __restrict__ src, const int* __restrict__ dst,
    const float* __restrict__ Wamul, const float* __restrict__ waout,
    const float* __restrict__ baout) {
    extern __shared__ float sm[];
    float* Ps = sm;                 // product tile [k][e]
    float* Ws = sm + D * PITCH;     // W_amul^T   [k][j]
    float* red = sm + 2 * D * PITCH; // [128][16] partial dot reductions
    __shared__ int ssrc[128], sdst[128];
    __shared__ float sw[D], sbias[D];
    int t = threadIdx.x;
    int e0 = blockIdx.x * 128;

    if (t < 128) {
        ssrc[t] = src[e0 + t];
        sdst[t] = dst[e0 + t];
        sw[t] = waout[t];
        sbias[t] = g_be[t];
    }
    {   // load W_amul transposed (no dependency on ssrc)
        int j = t >> 1, k0 = (t & 1) * 64;
#pragma unroll
        for (int k = k0; k < k0 + 64; k += 4) {
            float4 v = *(const float4*)&Wamul[j * D + k];
            Ws[(k + 0) * PITCH + j] = v.x;
            Ws[(k + 1) * PITCH + j] = v.y;
            Ws[(k + 2) * PITCH + j] = v.z;
            Ws[(k + 3) * PITCH + j] = v.w;
        }
    }
    __syncthreads();
    {   // gather fs, fd and form P = fs*fd
        int e = t >> 1, k0 = (t & 1) * 64;
        int sn = ssrc[e], dn = sdst[e];
        const float* rs = &feat[(size_t)sn * D];
        const float* rd = &feat[(size_t)dn * D];
#pragma unroll
        for (int k = k0; k < k0 + 64; k += 4) {
            float4 a = *(const float4*)&rs[k];
            float4 b = *(const float4*)&rd[k];
            Ps[(k + 0) * PITCH + e] = a.x * b.x;
            Ps[(k + 1) * PITCH + e] = a.y * b.y;
            Ps[(k + 2) * PITCH + e] = a.z * b.z;
            Ps[(k + 3) * PITCH + e] = a.w * b.w;
        }
    }
    __syncthreads();

    int ty = t >> 4, tx = t & 15, m0 = ty * 8, j0 = tx * 8;
    float acc[8][8];
#pragma unroll
    for (int i = 0; i < 8; i++)
#pragma unroll
        for (int j = 0; j < 8; j++) acc[i][j] = 0.f;

#pragma unroll 4
    for (int k = 0; k < D; k++) {
        float4 a0 = *(float4*)&Ps[k * PITCH + m0];
        float4 a1 = *(float4*)&Ps[k * PITCH + m0 + 4];
        float4 b0 = *(float4*)&Ws[k * PITCH + j0];
        float4 b1 = *(float4*)&Ws[k * PITCH + j0 + 4];
        float a[8] = {a0.x, a0.y, a0.z, a0.w, a1.x, a1.y, a1.z, a1.w};
        float b[8] = {b0.x, b0.y, b0.z, b0.w, b1.x, b1.y, b1.z, b1.w};
#pragma unroll
        for (int i = 0; i < 8; i++)
#pragma unroll
            for (int j = 0; j < 8; j++) acc[i][j] = fmaf(a[i], b[j], acc[i][j]);
    }

    // epilogue: e = gelu(P@W^T + S[src] + Dt[dst] + bias); partial dot with w_aout
#pragma unroll
    for (int i = 0; i < 8; i++) {
        int eL = m0 + i;
        int sn = ssrc[eL], dn = sdst[eL];
        float4 s0 = *(const float4*)&g_S[(size_t)sn * D + j0];
        float4 s1 = *(const float4*)&g_S[(size_t)sn * D + j0 + 4];
        float4 d0 = *(const float4*)&g_Dt[(size_t)dn * D + j0];
        float4 d1 = *(const float4*)&g_Dt[(size_t)dn * D + j0 + 4];
        float sarr[8] = {s0.x, s0.y, s0.z, s0.w, s1.x, s1.y, s1.z, s1.w};
        float darr[8] = {d0.x, d0.y, d0.z, d0.w, d1.x, d1.y, d1.z, d1.w};
        float p = 0.f;
#pragma unroll
        for (int j = 0; j < 8; j++) {
            float v = acc[i][j] + sarr[j] + darr[j] + sbias[j0 + j];
            p = fmaf(gelu_f(v), sw[j0 + j], p);
        }
        red[eL * 16 + tx] = p;
    }
    __syncthreads();
    if (t < 128) {
        float s = 0.f;
#pragma unroll
        for (int x = 0; x < 16; x++) s += red[t * 16 + x];
        s += baout[0];
        s = (s > 0.f) ? s : 0.2f * s;  // leaky_relu 0.2
        g_score[g_pos[e0 + t]] = s;     // write at CSR-sorted position
    }
}

// ---------------- stage 3: per-node aggregation (warp per node, no atomics) ----------------
__global__ void agg_kernel() {
    int gw = (blockIdx.x * blockDim.x + threadIdx.x) >> 5;
    int lane = threadIdx.x & 31;
    if (gw >= NN) return;
    int beg = g_rowptr[gw], end = g_rowptr[gw + 1];
    int off = lane * 4;
    float4 mx = make_float4(-FLT_MAX, -FLT_MAX, -FLT_MAX, -FLT_MAX);
    float4 sum = make_float4(0.f, 0.f, 0.f, 0.f);
    for (int p = beg; p < end; p++) {
        float sc = g_score[p];
        int sn = g_sbuf[p];
        float4 h = *(const float4*)&g_H[(size_t)sn * D + off];
        float4 h2 = *(const float4*)&g_H2[(size_t)sn * D + off];
        mx.x = fmaxf(mx.x, sc * h.x);
        mx.y = fmaxf(mx.y, sc * h.y);
        mx.z = fmaxf(mx.z, sc * h.z);
        mx.w = fmaxf(mx.w, sc * h.w);
        sum.x = fmaf(sc, h2.x, sum.x);
        sum.y = fmaf(sc, h2.y, sum.y);
        sum.z = fmaf(sc, h2.z, sum.z);
        sum.w = fmaf(sc, h2.w, sum.w);
    }
    int d = end - beg;
    if (d == 0) mx = make_float4(0.f, 0.f, 0.f, 0.f);
    float inv = 1.f / (float)(d > 1 ? d : 1);
    sum.x *= inv; sum.y *= inv; sum.z *= inv; sum.w *= inv;
    *(float4*)&g_neigh[(size_t)gw * D + off] = mx;
    *(float4*)&g_neigh2[(size_t)gw * D + off] = sum;
}

// ---------------- stage 4: output GEMMs + fused MLP residuals ----------------
__global__ __launch_bounds__(256, 1) void final_kernel(
    const float* __restrict__ feat,
    const float* __restrict__ Wself, const float* __restrict__ bself,
    const float* __restrict__ Wneigh, const float* __restrict__ bneigh,
    const float* __restrict__ Wneigh2, const float* __restrict__ bneigh2,
    const float* __restrict__ Wmlp, const float* __restrict__ bmlp,
    float* __restrict__ out) {
    extern __shared__ float sm[];
    float* As = sm;
    float* Bs = sm + D * PITCH;
    __shared__ float sb[D];
    int t = threadIdx.x;
    int base = blockIdx.x * 128;
    int ty = t >> 4, tx = t & 15, m0 = ty * 8, j0 = tx * 8;

    if (t < D) sb[t] = bself[t] + bneigh[t] + bneigh2[t];

    float acc[8][8];
#pragma unroll
    for (int i = 0; i < 8; i++)
#pragma unroll
        for (int j = 0; j < 8; j++) acc[i][j] = 0.f;

    for (int s = 0; s < 3; s++) {
        const float* X = (s == 0) ? feat : (s == 1) ? g_neigh : g_neigh2;
        const float* W = (s == 0) ? Wself : (s == 1) ? Wneigh : Wneigh2;
        __syncthreads();
        {
            int m = t >> 1, k0 = (t & 1) * 64;
            int node = base + m;
            if (node < NN) {
                const float* row = &X[(size_t)node * D];
#pragma unroll
                for (int k = k0; k < k0 + 64; k += 4) {
                    float4 v = *(const float4*)&row[k];
                    As[(k + 0) * PITCH + m] = v.x;
                    As[(k + 1) * PITCH + m] = v.y;
                    As[(k + 2) * PITCH + m] = v.z;
                    As[(k + 3) * PITCH + m] = v.w;
                }
            } else {
                for (int k = k0; k < k0 + 64; k++) As[k * PITCH + m] = 0.f;
            }
            int j = t >> 1;
            const float* wr = &W[j * D];
#pragma unroll
            for (int k = k0; k < k0 + 64; k += 4) {
                float4 v = *(const float4*)&wr[k];
                Bs[(k + 0) * PITCH + j] = v.x;
                Bs[(k + 1) * PITCH + j] = v.y;
                Bs[(k + 2) * PITCH + j] = v.z;
                Bs[(k + 3) * PITCH + j] = v.w;
            }
        }
        __syncthreads();
#pragma unroll 4
        for (int k = 0; k < D; k++) {
            float4 a0 = *(float4*)&As[k * PITCH + m0];
            float4 a1 = *(float4*)&As[k * PITCH + m0 + 4];
            float4 b0 = *(float4*)&Bs[k * PITCH + j0];
            float4 b1 = *(float4*)&Bs[k * PITCH + j0 + 4];
            float a[8] = {a0.x, a0.y, a0.z, a0.w, a1.x, a1.y, a1.z, a1.w};
            float b[8] = {b0.x, b0.y, b0.z, b0.w, b1.x, b1.y, b1.z, b1.w};
#pragma unroll
            for (int i = 0; i < 8; i++)
#pragma unroll
                for (int j = 0; j < 8; j++) acc[i][j] = fmaf(a[i], b[j], acc[i][j]);
        }
    }
    // add combined bias
#pragma unroll
    for (int i = 0; i < 8; i++)
#pragma unroll
        for (int j = 0; j < 8; j++) acc[i][j] += sb[j0 + j];

    // two residual MLP layers, fused (row-independent)
    for (int li = 0; li < 2; li++) {
        __syncthreads();
        // write gelu(rst) transposed into As:  Gs[k=out-dim][m=row]
#pragma unroll
        for (int i = 0; i < 8; i++)
#pragma unroll
            for (int j = 0; j < 8; j++)
                As[(j0 + j) * PITCH + (m0 + i)] = gelu_f(acc[i][j]);
        {
            int j = t >> 1, k0 = (t & 1) * 64;
            const float* wr = &Wmlp[(size_t)li * D * D + j * D];
#pragma unroll
            for (int k = k0; k < k0 + 64; k += 4) {
                float4 v = *(const float4*)&wr[k];
                Bs[(k + 0) * PITCH + j] = v.x;
                Bs[(k + 1) * PITCH + j] = v.y;
                Bs[(k + 2) * PITCH + j] = v.z;
                Bs[(k + 3) * PITCH + j] = v.w;
            }
            if (t < D) sb[t] = bmlp[li * D + t];
        }
        __syncthreads();
        float d2[8][8];
#pragma unroll
        for (int i = 0; i < 8; i++)
#pragma unroll
            for (int j = 0; j < 8; j++) d2[i][j] = 0.f;
#pragma unroll 4
        for (int k = 0; k < D; k++) {
            float4 a0 = *(float4*)&As[k * PITCH + m0];
            float4 a1 = *(float4*)&As[k * PITCH + m0 + 4];
            float4 b0 = *(float4*)&Bs[k * PITCH + j0];
            float4 b1 = *(float4*)&Bs[k * PITCH + j0 + 4];
            float a[8] = {a0.x, a0.y, a0.z, a0.w, a1.x, a1.y, a1.z, a1.w};
            float b[8] = {b0.x, b0.y, b0.z, b0.w, b1.x, b1.y, b1.z, b1.w};
#pragma unroll
            for (int i = 0; i < 8; i++)
#pragma unroll
                for (int j = 0; j < 8; j++) d2[i][j] = fmaf(a[i], b[j], d2[i][j]);
        }
#pragma unroll
        for (int i = 0; i < 8; i++)
#pragma unroll
            for (int j = 0; j < 8; j++) acc[i][j] += d2[i][j] + sb[j0 + j];
    }

#pragma unroll
    for (int i = 0; i < 8; i++) {
        int node = base + m0 + i;
        if (node >= NN) break;
        *(float4*)&out[(size_t)node * D + j0] =
            make_float4(acc[i][0], acc[i][1], acc[i][2], acc[i][3]);
        *(float4*)&out[(size_t)node * D + j0 + 4] =
            make_float4(acc[i][4], acc[i][5], acc[i][6], acc[i][7]);
    }
}

// ---------------- launch ----------------
extern "C" void kernel_launch(void* const* d_in, const int* in_sizes, int n_in,
                              void* d_out, int out_size) {
    const float* feat = (const float*)d_in[0];
    const int* src = (const int*)d_in[1];
    const int* dst = (const int*)d_in[2];
    const float* Wasrc = (const float*)d_in[3];
    const float* basrc = (const float*)d_in[4];
    const float* Wadst = (const float*)d_in[5];
    const float* badst = (const float*)d_in[6];
    const float* Wasub = (const float*)d_in[7];
    const float* basub = (const float*)d_in[8];
    const float* Wamul = (const float*)d_in[9];
    const float* bamul = (const float*)d_in[10];
    const float* Waout = (const float*)d_in[11];
    const float* baout = (const float*)d_in[12];
    const float* Wpool = (const float*)d_in[13];
    const float* bpool = (const float*)d_in[14];
    const float* Wpool2 = (const float*)d_in[15];
    const float* bpool2 = (const float*)d_in[16];
    const float* Wself = (const float*)d_in[17];
    const float* bself = (const float*)d_in[18];
    const float* Wneigh = (const float*)d_in[19];
    const float* bneigh = (const float*)d_in[20];
    const float* Wneigh2 = (const float*)d_in[21];
    const float* bneigh2 = (const float*)d_in[22];
    const float* Wmlp = (const float*)d_in[23];
    const float* bmlp = (const float*)d_in[24];
    float* out = (float*)d_out;

    const int SMEM_GEMM = 2 * D * PITCH * (int)sizeof(float);             // 135168
    const int SMEM_EDGE = SMEM_GEMM + 128 * 16 * (int)sizeof(float);      // 143360
    cudaFuncSetAttribute(node1_kernel, cudaFuncAttributeMaxDynamicSharedMemorySize, SMEM_GEMM);
    cudaFuncSetAttribute(edge_kernel, cudaFuncAttributeMaxDynamicSharedMemorySize, SMEM_EDGE);
    cudaFuncSetAttribute(final_kernel, cudaFuncAttributeMaxDynamicSharedMemorySize, SMEM_GEMM);

    prep_kernel<<<64, 256>>>(Wasrc, Wadst, Wasub, basrc, badst, basub, bamul);
    init_deg_kernel<<<(NN + 255) / 256, 256>>>();
    deg_kernel<<<(NE + 255) / 256, 256>>>(dst);
    scan_kernel<<<1, 1024>>>();
    fill_kernel<<<(NE + 255) / 256, 256>>>(src, dst);
    node1_kernel<<<(NN + 127) / 128, 256, SMEM_GEMM>>>(feat, Wpool, bpool, Wpool2, bpool2);
    edge_kernel<<<NE / 128, 256, SMEM_EDGE>>>(feat, src, dst, Wamul, Waout, baout);
    agg_kernel<<<(NN * 32 + 255) / 256, 256>>>();
    final_kernel<<<(NN + 127) / 128, 256, SMEM_GEMM>>>(feat, Wself, bself, Wneigh, bneigh,
                                                       Wneigh2, bneigh2, Wmlp, bmlp, out);
}

// round 2
// speedup vs baseline: 1.0000x; 1.0000x over previous
#include <cuda_runtime.h>
#include <math.h>
#include <float.h>

#define NN 50000
#define NE 800000
#define D 128
#define PITCH 132   // smem pitch in floats (multiple of 4, avoids worst bank patterns)

// ---------------- scratch (static device globals: allocation-free) ----------------
__device__ float g_S[NN * D];       // feat @ (W_asrc+W_asub)^T
__device__ float g_Dt[NN * D];      // feat @ (W_adst-W_asub)^T
__device__ float g_H[NN * D];       // gelu(feat@W_pool^T + b_pool)
__device__ float g_H2[NN * D];      // gelu(feat@W_pool2^T + b_pool2)
__device__ float g_neigh[NN * D];
__device__ float g_neigh2[NN * D];
__device__ int   g_deg[NN];
__device__ int   g_rowptr[NN + 1];
__device__ int   g_cursor[NN];
__device__ int   g_sbuf[NE];        // src node id at sorted (CSR) position
__device__ int   g_pos[NE];         // edge e -> CSR position
__device__ float g_score[NE];       // attention score at sorted position
__device__ float g_WS[D * D];
__device__ float g_WD[D * D];
__device__ float g_be[D];           // combined bias for e

__device__ __forceinline__ float gelu_f(float x) {
    return 0.5f * x * (1.0f + erff(x * 0.70710678118654752f));
}

// ---------------- tiny prep kernels ----------------
__global__ void prep_kernel(const float* __restrict__ Wasrc, const float* __restrict__ Wadst,
                            const float* __restrict__ Wasub,
                            const float* __restrict__ basrc, const float* __restrict__ badst,
                            const float* __restrict__ basub, const float* __restrict__ bamul) {
    int i = blockIdx.x * blockDim.x + threadIdx.x;
    if (i < D * D) {
        g_WS[i] = Wasrc[i] + Wasub[i];
        g_WD[i] = Wadst[i] - Wasub[i];
    }
    if (i < D) g_be[i] = basrc[i] + badst[i] + basub[i] + bamul[i];
}

__global__ void init_deg_kernel() {
    int i = blockIdx.x * blockDim.x + threadIdx.x;
    if (i < NN) g_deg[i] = 0;
}

__global__ void deg_kernel(const int* __restrict__ dst) {
    int e = blockIdx.x * blockDim.x + threadIdx.x;
    if (e < NE) atomicAdd(&g_deg[dst[e]], 1);
}

// single-block exclusive scan over 50000 degrees -> rowptr, cursor
__global__ void scan_kernel() {
    __shared__ int part[1024];
    int t = threadIdx.x;
    const int CH = (NN + 1023) / 1024;
    int start = t * CH;
    int s = 0;
    for (int i = 0; i < CH; i++) {
        int idx = start + i;
        if (idx < NN) s += g_deg[idx];
    }
    part[t] = s;
    __syncthreads();
    for (int off = 1; off < 1024; off <<= 1) {
        int v = (t >= off) ? part[t - off] : 0;
        __syncthreads();
        part[t] += v;
        __syncthreads();
    }
    int base = (t == 0) ? 0 : part[t - 1];
    for (int i = 0; i < CH; i++) {
        int idx = start + i;
        if (idx < NN) {
            g_rowptr[idx] = base;
            g_cursor[idx] = base;
            base += g_deg[idx];
        }
    }
    if (t == 1023) g_rowptr[NN] = part[1023];
}

__global__ void fill_kernel(const int* __restrict__ src, const int* __restrict__ dst) {
    int e = blockIdx.x * blockDim.x + threadIdx.x;
    if (e < NE) {
        int p = atomicAdd(&g_cursor[dst[e]], 1);
        g_sbuf[p] = src[e];
        g_pos[e] = p;
    }
}

// ---------------- stage 1: node GEMMs (S, Dt, H, H2) ----------------
__global__ __launch_bounds__(256, 1) void node1_kernel(
    const float* __restrict__ feat,
    const float* __restrict__ Wpool, const float* __restrict__ bpool,
    const float* __restrict__ Wpool2, const float* __restrict__ bpool2) {
    extern __shared__ float sm[];
    float* As = sm;               // [k][m] 128 x PITCH
    float* Bs = sm + D * PITCH;   // [k][j]
    __shared__ float sbias[D];
    int t = threadIdx.x;
    int base = blockIdx.x * 128;

    {   // load A tile transposed
        int m = t >> 1, k0 = (t & 1) * 64;
        int node = base + m;
        if (node < NN) {
            const float* row = &feat[(size_t)node * D];
#pragma unroll
            for (int k = k0; k < k0 + 64; k += 4) {
                float4 v = *(const float4*)&row[k];
                As[(k + 0) * PITCH + m] = v.x;
                As[(k + 1) * PITCH + m] = v.y;
                As[(k + 2) * PITCH + m] = v.z;
                As[(k + 3) * PITCH + m] = v.w;
            }
        } else {
            for (int k = k0; k < k0 + 64; k++) As[k * PITCH + m] = 0.f;
        }
    }
    int ty = t >> 4, tx = t & 15, m0 = ty * 8, j0 = tx * 8;

    for (int mat = 0; mat < 4; mat++) {
        const float* W = (mat == 0) ? g_WS : (mat == 1) ? g_WD : (mat == 2) ? Wpool : Wpool2;
        __syncthreads();
        {
            int j = t >> 1, k0 = (t & 1) * 64;
            const float* wr = &W[j * D];
#pragma unroll
            for (int k = k0; k < k0 + 64; k += 4) {
                float4 v = *(const float4*)&wr[k];
                Bs[(k + 0) * PITCH + j] = v.x;
                Bs[(k + 1) * PITCH + j] = v.y;
                Bs[(k + 2) * PITCH + j] = v.z;
                Bs[(k + 3) * PITCH + j] = v.w;
            }
            if (t < D) sbias[t] = (mat == 2) ? bpool[t] : (mat == 3) ? bpool2[t] : 0.f;
        }
        __syncthreads();

        float acc[8][8];
#pragma unroll
        for (int i = 0; i < 8; i++)
#pragma unroll
            for (int j = 0; j < 8; j++) acc[i][j] = 0.f;

#pragma unroll 4
        for (int k = 0; k < D; k++) {
            float4 a0 = *(float4*)&As[k * PITCH + m0];
            float4 a1 = *(float4*)&As[k * PITCH + m0 + 4];
            float4 b0 = *(float4*)&Bs[k * PITCH + j0];
            float4 b1 = *(float4*)&Bs[k * PITCH + j0 + 4];
            float a[8] = {a0.x, a0.y, a0.z, a0.w, a1.x, a1.y, a1.z, a1.w};
            float b[8] = {b0.x, b0.y, b0.z, b0.w, b1.x, b1.y, b1.z, b1.w};
#pragma unroll
            for (int i = 0; i < 8; i++)
#pragma unroll
                for (int j = 0; j < 8; j++) acc[i][j] = fmaf(a[i], b[j], acc[i][j]);
        }

        float* OUT = (mat == 0) ? g_S : (mat == 1) ? g_Dt : (mat == 2) ? g_H : g_H2;
#pragma unroll
        for (int i = 0; i < 8; i++) {
            int node = base + m0 + i;
            if (node >= NN) break;
            float o[8];
#pragma unroll
            for (int j = 0; j < 8; j++) {
                float v = acc[i][j];
                if (mat >= 2) v = gelu_f(v + sbias[j0 + j]);
                o[j] = v;
            }
            *(float4*)&OUT[(size_t)node * D + j0] = make_float4(o[0], o[1], o[2], o[3]);
            *(float4*)&OUT[(size_t)node * D + j0 + 4] = make_float4(o[4], o[5], o[6], o[7]);
        }
    }
}

// ---------------- stage 2: edge attention scores ----------------
__global__ __launch_bounds__(256, 1) void edge_kernel(
    const float* __restrict__ feat, const int* __restrict__ src, const int* __restrict__ dst,
    const float* __restrict__ Wamul, const float* __restrict__ waout,
    const float* __restrict__ baout) {
    extern __shared__ float sm[];
    float* Ps = sm;                 // product tile [k][e]
    float* Ws = sm + D * PITCH;     // W_amul^T   [k][j]
    float* red = sm + 2 * D * PITCH; // [128][16] partial dot reductions
    __shared__ int ssrc[128], sdst[128];
    __shared__ float sw[D], sbias[D];
    int t = threadIdx.x;
    int e0 = blockIdx.x * 128;

    if (t < 128) {
        ssrc[t] = src[e0 + t];
        sdst[t] = dst[e0 + t];
        sw[t] = waout[t];
        sbias[t] = g_be[t];
    }
    {   // load W_amul transposed (no dependency on ssrc)
        int j = t >> 1, k0 = (t & 1) * 64;
#pragma unroll
        for (int k = k0; k < k0 + 64; k += 4) {
            float4 v = *(const float4*)&Wamul[j * D + k];
            Ws[(k + 0) * PITCH + j] = v.x;
            Ws[(k + 1) * PITCH + j] = v.y;
            Ws[(k + 2) * PITCH + j] = v.z;
            Ws[(k + 3) * PITCH + j] = v.w;
        }
    }
    __syncthreads();
    {   // gather fs, fd and form P = fs*fd
        int e = t >> 1, k0 = (t & 1) * 64;
        int sn = ssrc[e], dn = sdst[e];
        const float* rs = &feat[(size_t)sn * D];
        const float* rd = &feat[(size_t)dn * D];
#pragma unroll
        for (int k = k0; k < k0 + 64; k += 4) {
            float4 a = *(const float4*)&rs[k];
            float4 b = *(const float4*)&rd[k];
            Ps[(k + 0) * PITCH + e] = a.x * b.x;
            Ps[(k + 1) * PITCH + e] = a.y * b.y;
            Ps[(k + 2) * PITCH + e] = a.z * b.z;
            Ps[(k + 3) * PITCH + e] = a.w * b.w;
        }
    }
    __syncthreads();

    int ty = t >> 4, tx = t & 15, m0 = ty * 8, j0 = tx * 8;
    float acc[8][8];
#pragma unroll
    for (int i = 0; i < 8; i++)
#pragma unroll
        for (int j = 0; j < 8; j++) acc[i][j] = 0.f;

#pragma unroll 4
    for (int k = 0; k < D; k++) {
        float4 a0 = *(float4*)&Ps[k * PITCH + m0];
        float4 a1 = *(float4*)&Ps[k * PITCH + m0 + 4];
        float4 b0 = *(float4*)&Ws[k * PITCH + j0];
        float4 b1 = *(float4*)&Ws[k * PITCH + j0 + 4];
        float a[8] = {a0.x, a0.y, a0.z, a0.w, a1.x, a1.y, a1.z, a1.w};
        float b[8] = {b0.x, b0.y, b0.z, b0.w, b1.x, b1.y, b1.z, b1.w};
#pragma unroll
        for (int i = 0; i < 8; i++)
#pragma unroll
            for (int j = 0; j < 8; j++) acc[i][j] = fmaf(a[i], b[j], acc[i][j]);
    }

    // epilogue: e = gelu(P@W^T + S[src] + Dt[dst] + bias); partial dot with w_aout
#pragma unroll
    for (int i = 0; i < 8; i++) {
        int eL = m0 + i;
        int sn = ssrc[eL], dn = sdst[eL];
        float4 s0 = *(const float4*)&g_S[(size_t)sn * D + j0];
        float4 s1 = *(const float4*)&g_S[(size_t)sn * D + j0 + 4];
        float4 d0 = *(const float4*)&g_Dt[(size_t)dn * D + j0];
        float4 d1 = *(const float4*)&g_Dt[(size_t)dn * D + j0 + 4];
        float sarr[8] = {s0.x, s0.y, s0.z, s0.w, s1.x, s1.y, s1.z, s1.w};
        float darr[8] = {d0.x, d0.y, d0.z, d0.w, d1.x, d1.y, d1.z, d1.w};
        float p = 0.f;
#pragma unroll
        for (int j = 0; j < 8; j++) {
            float v = acc[i][j] + sarr[j] + darr[j] + sbias[j0 + j];
            p = fmaf(gelu_f(v), sw[j0 + j], p);
        }
        red[eL * 16 + tx] = p;
    }
    __syncthreads();
    if (t < 128) {
        float s = 0.f;
#pragma unroll
        for (int x = 0; x < 16; x++) s += red[t * 16 + x];
        s += baout[0];
        s = (s > 0.f) ? s : 0.2f * s;  // leaky_relu 0.2
        g_score[g_pos[e0 + t]] = s;     // write at CSR-sorted position
    }
}

// ---------------- stage 3: per-node aggregation (warp per node, no atomics) ----------------
__global__ void agg_kernel() {
    int gw = (blockIdx.x * blockDim.x + threadIdx.x) >> 5;
    int lane = threadIdx.x & 31;
    if (gw >= NN) return;
    int beg = g_rowptr[gw], end = g_rowptr[gw + 1];
    int off = lane * 4;
    float4 mx = make_float4(-FLT_MAX, -FLT_MAX, -FLT_MAX, -FLT_MAX);
    float4 sum = make_float4(0.f, 0.f, 0.f, 0.f);
    for (int p = beg; p < end; p++) {
        float sc = g_score[p];
        int sn = g_sbuf[p];
        float4 h = *(const float4*)&g_H[(size_t)sn * D + off];
        float4 h2 = *(const float4*)&g_H2[(size_t)sn * D + off];
        mx.x = fmaxf(mx.x, sc * h.x);
        mx.y = fmaxf(mx.y, sc * h.y);
        mx.z = fmaxf(mx.z, sc * h.z);
        mx.w = fmaxf(mx.w, sc * h.w);
        sum.x = fmaf(sc, h2.x, sum.x);
        sum.y = fmaf(sc, h2.y, sum.y);
        sum.z = fmaf(sc, h2.z, sum.z);
        sum.w = fmaf(sc, h2.w, sum.w);
    }
    int d = end - beg;
    if (d == 0) mx = make_float4(0.f, 0.f, 0.f, 0.f);
    float inv = 1.f / (float)(d > 1 ? d : 1);
    sum.x *= inv; sum.y *= inv; sum.z *= inv; sum.w *= inv;
    *(float4*)&g_neigh[(size_t)gw * D + off] = mx;
    *(float4*)&g_neigh2[(size_t)gw * D + off] = sum;
}

// ---------------- stage 4: output GEMMs + fused MLP residuals ----------------
__global__ __launch_bounds__(256, 1) void final_kernel(
    const float* __restrict__ feat,
    const float* __restrict__ Wself, const float* __restrict__ bself,
    const float* __restrict__ Wneigh, const float* __restrict__ bneigh,
    const float* __restrict__ Wneigh2, const float* __restrict__ bneigh2,
    const float* __restrict__ Wmlp, const float* __restrict__ bmlp,
    float* __restrict__ out) {
    extern __shared__ float sm[];
    float* As = sm;
    float* Bs = sm + D * PITCH;
    __shared__ float sb[D];
    int t = threadIdx.x;
    int base = blockIdx.x * 128;
    int ty = t >> 4, tx = t & 15, m0 = ty * 8, j0 = tx * 8;

    if (t < D) sb[t] = bself[t] + bneigh[t] + bneigh2[t];

    float acc[8][8];
#pragma unroll
    for (int i = 0; i < 8; i++)
#pragma unroll
        for (int j = 0; j < 8; j++) acc[i][j] = 0.f;

    for (int s = 0; s < 3; s++) {
        const float* X = (s == 0) ? feat : (s == 1) ? g_neigh : g_neigh2;
        const float* W = (s == 0) ? Wself : (s == 1) ? Wneigh : Wneigh2;
        __syncthreads();
        {
            int m = t >> 1, k0 = (t & 1) * 64;
            int node = base + m;
            if (node < NN) {
                const float* row = &X[(size_t)node * D];
#pragma unroll
                for (int k = k0; k < k0 + 64; k += 4) {
                    float4 v = *(const float4*)&row[k];
                    As[(k + 0) * PITCH + m] = v.x;
                    As[(k + 1) * PITCH + m] = v.y;
                    As[(k + 2) * PITCH + m] = v.z;
                    As[(k + 3) * PITCH + m] = v.w;
                }
            } else {
                for (int k = k0; k < k0 + 64; k++) As[k * PITCH + m] = 0.f;
            }
            int j = t >> 1;
            const float* wr = &W[j * D];
#pragma unroll
            for (int k = k0; k < k0 + 64; k += 4) {
                float4 v = *(const float4*)&wr[k];
                Bs[(k + 0) * PITCH + j] = v.x;
                Bs[(k + 1) * PITCH + j] = v.y;
                Bs[(k + 2) * PITCH + j] = v.z;
                Bs[(k + 3) * PITCH + j] = v.w;
            }
        }
        __syncthreads();
#pragma unroll 4
        for (int k = 0; k < D; k++) {
            float4 a0 = *(float4*)&As[k * PITCH + m0];
            float4 a1 = *(float4*)&As[k * PITCH + m0 + 4];
            float4 b0 = *(float4*)&Bs[k * PITCH + j0];
            float4 b1 = *(float4*)&Bs[k * PITCH + j0 + 4];
            float a[8] = {a0.x, a0.y, a0.z, a0.w, a1.x, a1.y, a1.z, a1.w};
            float b[8] = {b0.x, b0.y, b0.z, b0.w, b1.x, b1.y, b1.z, b1.w};
#pragma unroll
            for (int i = 0; i < 8; i++)
#pragma unroll
                for (int j = 0; j < 8; j++) acc[i][j] = fmaf(a[i], b[j], acc[i][j]);
        }
    }
    // add combined bias
#pragma unroll
    for (int i = 0; i < 8; i++)
#pragma unroll
        for (int j = 0; j < 8; j++) acc[i][j] += sb[j0 + j];

    // two residual MLP layers, fused (row-independent)
    for (int li = 0; li < 2; li++) {
        __syncthreads();
        // write gelu(rst) transposed into As:  Gs[k=out-dim][m=row]
#pragma unroll
        for (int i = 0; i < 8; i++)
#pragma unroll
            for (int j = 0; j < 8; j++)
                As[(j0 + j) * PITCH + (m0 + i)] = gelu_f(acc[i][j]);
        {
            int j = t >> 1, k0 = (t & 1) * 64;
            const float* wr = &Wmlp[(size_t)li * D * D + j * D];
#pragma unroll
            for (int k = k0; k < k0 + 64; k += 4) {
                float4 v = *(const float4*)&wr[k];
                Bs[(k + 0) * PITCH + j] = v.x;
                Bs[(k + 1) * PITCH + j] = v.y;
                Bs[(k + 2) * PITCH + j] = v.z;
                Bs[(k + 3) * PITCH + j] = v.w;
            }
            if (t < D) sb[t] = bmlp[li * D + t];
        }
        __syncthreads();
        float d2[8][8];
#pragma unroll
        for (int i = 0; i < 8; i++)
#pragma unroll
            for (int j = 0; j < 8; j++) d2[i][j] = 0.f;
#pragma unroll 4
        for (int k = 0; k < D; k++) {
            float4 a0 = *(float4*)&As[k * PITCH + m0];
            float4 a1 = *(float4*)&As[k * PITCH + m0 + 4];
            float4 b0 = *(float4*)&Bs[k * PITCH + j0];
            float4 b1 = *(float4*)&Bs[k * PITCH + j0 + 4];
            float a[8] = {a0.x, a0.y, a0.z, a0.w, a1.x, a1.y, a1.z, a1.w};
            float b[8] = {b0.x, b0.y, b0.z, b0.w, b1.x, b1.y, b1.z, b1.w};
#pragma unroll
            for (int i = 0; i < 8; i++)
#pragma unroll
                for (int j = 0; j < 8; j++) d2[i][j] = fmaf(a[i], b[j], d2[i][j]);
        }
#pragma unroll
        for (int i = 0; i < 8; i++)
#pragma unroll
            for (int j = 0; j < 8; j++) acc[i][j] += d2[i][j] + sb[j0 + j];
    }

#pragma unroll
    for (int i = 0; i < 8; i++) {
        int node = base + m0 + i;
        if (node >= NN) break;
        *(float4*)&out[(size_t)node * D + j0] =
            make_float4(acc[i][0], acc[i][1], acc[i][2], acc[i][3]);
        *(float4*)&out[(size_t)node * D + j0 + 4] =
            make_float4(acc[i][4], acc[i][5], acc[i][6], acc[i][7]);
    }
}

// ---------------- launch ----------------
extern "C" void kernel_launch(void* const* d_in, const int* in_sizes, int n_in,
                              void* d_out, int out_size) {
    const float* feat = (const float*)d_in[0];
    const int* src = (const int*)d_in[1];
    const int* dst = (const int*)d_in[2];
    const float* Wasrc = (const float*)d_in[3];
    const float* basrc = (const float*)d_in[4];
    const float* Wadst = (const float*)d_in[5];
    const float* badst = (const float*)d_in[6];
    const float* Wasub = (const float*)d_in[7];
    const float* basub = (const float*)d_in[8];
    const float* Wamul = (const float*)d_in[9];
    const float* bamul = (const float*)d_in[10];
    const float* Waout = (const float*)d_in[11];
    const float* baout = (const float*)d_in[12];
    const float* Wpool = (const float*)d_in[13];
    const float* bpool = (const float*)d_in[14];
    const float* Wpool2 = (const float*)d_in[15];
    const float* bpool2 = (const float*)d_in[16];
    const float* Wself = (const float*)d_in[17];
    const float* bself = (const float*)d_in[18];
    const float* Wneigh = (const float*)d_in[19];
    const float* bneigh = (const float*)d_in[20];
    const float* Wneigh2 = (const float*)d_in[21];
    const float* bneigh2 = (const float*)d_in[22];
    const float* Wmlp = (const float*)d_in[23];
    const float* bmlp = (const float*)d_in[24];
    float* out = (float*)d_out;

    const int SMEM_GEMM = 2 * D * PITCH * (int)sizeof(float);             // 135168
    const int SMEM_EDGE = SMEM_GEMM + 128 * 16 * (int)sizeof(float);      // 143360
    cudaFuncSetAttribute(node1_kernel, cudaFuncAttributeMaxDynamicSharedMemorySize, SMEM_GEMM);
    cudaFuncSetAttribute(edge_kernel, cudaFuncAttributeMaxDynamicSharedMemorySize, SMEM_EDGE);
    cudaFuncSetAttribute(final_kernel, cudaFuncAttributeMaxDynamicSharedMemorySize, SMEM_GEMM);

    prep_kernel<<<64, 256>>>(Wasrc, Wadst, Wasub, basrc, badst, basub, bamul);
    init_deg_kernel<<<(NN + 255) / 256, 256>>>();
    deg_kernel<<<(NE + 255) / 256, 256>>>(dst);
    scan_kernel<<<1, 1024>>>();
    fill_kernel<<<(NE + 255) / 256, 256>>>(src, dst);
    node1_kernel<<<(NN + 127) / 128, 256, SMEM_GEMM>>>(feat, Wpool, bpool, Wpool2, bpool2);
    edge_kernel<<<NE / 128, 256, SMEM_EDGE>>>(feat, src, dst, Wamul, Waout, baout);
    agg_kernel<<<(NN * 32 + 255) / 256, 256>>>();
    final_kernel<<<(NN + 127) / 128, 256, SMEM_GEMM>>>(feat, Wself, bself, Wneigh, bneigh,
                                                       Wneigh2, bneigh2, Wmlp, bmlp, out);
}

// round 5
// speedup vs baseline: 1.8121x; 1.8120x over previous
#include <cuda_runtime.h>
#include <cstdint>
#include <math.h>
#include <float.h>

#define NN 50000
#define NE 800000
#define D 128
#define PITCH 132
#define NBLK 196

__device__ float g_S[NN * D];
__device__ float g_Dt[NN * D];
__device__ float g_H[NN * D];
__device__ float g_H2[NN * D];
__device__ float g_neigh[NN * D];
__device__ float g_neigh2[NN * D];
__device__ int   g_deg[NN];
__device__ int   g_rowptr[NN + 1];
__device__ int   g_cursor[NN];
__device__ int   g_scantmp[NN];
__device__ int   g_bsum[256];
__device__ int   g_bbase[256];
__device__ int   g_sbuf[NE];
__device__ int   g_dbuf[NE];
__device__ float g_score[NE];
__device__ float g_WS[D * D];
__device__ float g_WD[D * D];
__device__ float g_be[D];

__device__ __forceinline__ float tf32r(float x) {
    uint32_t r; asm("cvt.rna.tf32.f32 %0, %1;" : "=r"(r) : "f"(x));
    return __uint_as_float(r);
}
__device__ __forceinline__ float gelu_f(float x) {
    return 0.5f * x * (1.0f + erff(x * 0.70710678118654752f));
}
__device__ __forceinline__ void mma8(float* c, const uint32_t* a, uint32_t b0, uint32_t b1) {
    asm volatile("mma.sync.aligned.m16n8k8.row.col.f32.tf32.tf32.f32 "
                 "{%0,%1,%2,%3},{%4,%5,%6,%7},{%8,%9},{%0,%1,%2,%3};"
                 : "+f"(c[0]), "+f"(c[1]), "+f"(c[2]), "+f"(c[3])
                 : "r"(a[0]), "r"(a[1]), "r"(a[2]), "r"(a[3]), "r"(b0), "r"(b1));
}

// warp-tile m32 x n64 over K=128 from padded row-major smem tiles.
// acc[mi*8+ni][4]; A "row": As[row][k]; B "col": Bs[j][k] (weights are [out][in]).
__device__ __forceinline__ void gemm_tile(const float* As, const float* Bs,
                                          int wr, int wc, int lane, float (*acc)[4]) {
    int r = lane >> 2, c = lane & 3;
#pragma unroll
    for (int ks = 0; ks < 16; ks++) {
        uint32_t a[2][4];
#pragma unroll
        for (int mi = 0; mi < 2; mi++) {
            const float* Ap = As + (wr * 32 + mi * 16 + r) * PITCH + ks * 8 + c;
            a[mi][0] = __float_as_uint(Ap[0]);
            a[mi][1] = __float_as_uint(Ap[8 * PITCH]);
            a[mi][2] = __float_as_uint(Ap[4]);
            a[mi][3] = __float_as_uint(Ap[8 * PITCH + 4]);
        }
#pragma unroll
        for (int ni = 0; ni < 8; ni++) {
            const float* Bp = Bs + (wc * 64 + ni * 8 + r) * PITCH + ks * 8 + c;
            uint32_t b0 = __float_as_uint(Bp[0]);
            uint32_t b1 = __float_as_uint(Bp[4]);
            mma8(acc[ni], a[0], b0, b1);
            mma8(acc[8 + ni], a[1], b0, b1);
        }
    }
}

// stage one weight matrix [D][D] row-major -> Bs padded, tf32-rounded (256 threads)
__device__ __forceinline__ void stage_B(float* Bs, const float* W, int t) {
    int j = t >> 1, k0 = (t & 1) * 64;
    const float* wr_ = W + j * D + k0;
    float* bp = Bs + j * PITCH + k0;
#pragma unroll
    for (int k = 0; k < 64; k += 4) {
        float4 v = *(const float4*)(wr_ + k);
        bp[k] = tf32r(v.x); bp[k + 1] = tf32r(v.y);
        bp[k + 2] = tf32r(v.z); bp[k + 3] = tf32r(v.w);
    }
}

// ---------------- prep ----------------
__global__ void prep_kernel(const float* __restrict__ Wasrc, const float* __restrict__ Wadst,
                            const float* __restrict__ Wasub,
                            const float* __restrict__ basrc, const float* __restrict__ badst,
                            const float* __restrict__ basub, const float* __restrict__ bamul) {
    int i = blockIdx.x * blockDim.x + threadIdx.x;
    if (i < D * D) {
        g_WS[i] = Wasrc[i] + Wasub[i];
        g_WD[i] = Wadst[i] - Wasub[i];
    }
    if (i < D) g_be[i] = basrc[i] + badst[i] + basub[i] + bamul[i];
}

// ---------------- CSR build ----------------
__global__ void init_deg_kernel() {
    int i = blockIdx.x * blockDim.x + threadIdx.x;
    if (i < NN) g_deg[i] = 0;
}
__global__ void deg_kernel(const int* __restrict__ dst) {
    int e = blockIdx.x * blockDim.x + threadIdx.x;
    if (e < NE) atomicAdd(&g_deg[dst[e]], 1);
}
__device__ __forceinline__ int block_incl_scan(int v, int t) {
    int lane = t & 31, w = t >> 5;
    int x = v;
#pragma unroll
    for (int o = 1; o < 32; o <<= 1) {
        int y = __shfl_up_sync(0xffffffffu, x, o);
        if (lane >= o) x += y;
    }
    __shared__ int ws[8];
    if (lane == 31) ws[w] = x;
    __syncthreads();
    if (t == 0) {
        int s = 0;
#pragma unroll
        for (int k = 0; k < 8; k++) { int tmp = ws[k]; ws[k] = s; s += tmp; }
    }
    __syncthreads();
    return x + ws[w];
}
__global__ void scan1_kernel() {
    int b = blockIdx.x, t = threadIdx.x, i = b * 256 + t;
    int v = (i < NN) ? g_deg[i] : 0;
    int x = block_incl_scan(v, t);
    if (i < NN) g_scantmp[i] = x;
    if (t == 255) g_bsum[b] = x;
}
__global__ void scan2_kernel() {
    int t = threadIdx.x;
    int v = (t < NBLK) ? g_bsum[t] : 0;
    int x = block_incl_scan(v, t);
    g_bbase[t] = x - v;
}
__global__ void scan3_kernel() {
    int b = blockIdx.x, t = threadIdx.x, i = b * 256 + t;
    if (i < NN) {
        int ex = g_scantmp[i] - g_deg[i] + g_bbase[b];
        g_rowptr[i] = ex;
        g_cursor[i] = ex;
        if (i == NN - 1) g_rowptr[NN] = ex + g_deg[i];
    }
}
__global__ void fill_kernel(const int* __restrict__ src, const int* __restrict__ dst) {
    int e = blockIdx.x * blockDim.x + threadIdx.x;
    if (e < NE) {
        int dn = dst[e];
        int p = atomicAdd(&g_cursor[dn], 1);
        g_sbuf[p] = src[e];
        g_dbuf[p] = dn;
    }
}

// ---------------- stage 1: node GEMMs (S, Dt, H, H2) ----------------
__global__ __launch_bounds__(256, 1) void node_mma(const float* __restrict__ feat,
                                                   const float* __restrict__ Wpool,
                                                   const float* __restrict__ bpool,
                                                   const float* __restrict__ Wpool2,
                                                   const float* __restrict__ bpool2) {
    extern __shared__ float sm[];
    float* As = sm;
    float* Bs = sm + D * PITCH;
    __shared__ float sbias[D];
    int t = threadIdx.x, lane = t & 31, warp = t >> 5;
    int wr = warp >> 1, wc = warp & 1;
    int base = blockIdx.x * 128;

    {   // stage A = feat rows (tf32)
        int row = t >> 1, k0 = (t & 1) * 64;
        int node = base + row;
        float* ap = As + row * PITCH + k0;
        if (node < NN) {
            const float* fr = feat + (size_t)node * D + k0;
#pragma unroll
            for (int k = 0; k < 64; k += 4) {
                float4 v = *(const float4*)(fr + k);
                ap[k] = tf32r(v.x); ap[k + 1] = tf32r(v.y);
                ap[k + 2] = tf32r(v.z); ap[k + 3] = tf32r(v.w);
            }
        } else {
            for (int k = 0; k < 64; k++) ap[k] = 0.f;
        }
    }
    int r = lane >> 2, c = lane & 3;
    for (int mat = 0; mat < 4; mat++) {
        const float* W = mat == 0 ? g_WS : mat == 1 ? g_WD : mat == 2 ? Wpool : Wpool2;
        __syncthreads();
        stage_B(Bs, W, t);
        if (t < D) sbias[t] = (mat == 2) ? bpool[t] : (mat == 3) ? bpool2[t] : 0.f;
        __syncthreads();
        float acc[16][4];
#pragma unroll
        for (int i = 0; i < 16; i++)
#pragma unroll
            for (int q = 0; q < 4; q++) acc[i][q] = 0.f;
        gemm_tile(As, Bs, wr, wc, lane, acc);
        float* OUT = mat == 0 ? g_S : mat == 1 ? g_Dt : mat == 2 ? g_H : g_H2;
#pragma unroll
        for (int mi = 0; mi < 2; mi++)
#pragma unroll
            for (int h = 0; h < 2; h++) {
                int node = base + wr * 32 + mi * 16 + r + h * 8;
                if (node < NN) {
#pragma unroll
                    for (int ni = 0; ni < 8; ni++) {
                        int col = wc * 64 + ni * 8 + 2 * c;
                        float v0 = acc[mi * 8 + ni][h * 2 + 0];
                        float v1 = acc[mi * 8 + ni][h * 2 + 1];
                        if (mat >= 2) {
                            v0 = gelu_f(v0 + sbias[col]);
                            v1 = gelu_f(v1 + sbias[col + 1]);
                        }
                        *(float2*)(OUT + (size_t)node * D + col) = make_float2(v0, v1);
                    }
                }
            }
    }
}

// ---------------- stage 2: edge scores (CSR order) ----------------
__global__ __launch_bounds__(256, 1) void edge_mma(const float* __restrict__ feat,
                                                   const float* __restrict__ Wamul,
                                                   const float* __restrict__ waout,
                                                   const float* __restrict__ baout) {
    extern __shared__ float sm[];
    float* As = sm;
    float* Bs = sm + D * PITCH;
    float* red = sm + 2 * D * PITCH;   // [128][8]
    __shared__ int ssrc[128], sdst_[128];
    __shared__ float sbias[D], sw[D];
    int t = threadIdx.x, lane = t & 31, warp = t >> 5;
    int wr = warp >> 1, wc = warp & 1;
    int p0 = blockIdx.x * 128;

    if (t < 128) {
        ssrc[t] = g_sbuf[p0 + t];
        sdst_[t] = g_dbuf[p0 + t];
        sbias[t] = g_be[t];
        sw[t] = waout[t];
    }
    stage_B(Bs, Wamul, t);
    __syncthreads();
    {   // stage A = fs*fd (tf32)
        int row = t >> 1, k0 = (t & 1) * 64;
        const float* rs = feat + (size_t)ssrc[row] * D + k0;
        const float* rd = feat + (size_t)sdst_[row] * D + k0;
        float* ap = As + row * PITCH + k0;
#pragma unroll
        for (int k = 0; k < 64; k += 4) {
            float4 a = *(const float4*)(rs + k);
            float4 b = *(const float4*)(rd + k);
            ap[k] = tf32r(a.x * b.x); ap[k + 1] = tf32r(a.y * b.y);
            ap[k + 2] = tf32r(a.z * b.z); ap[k + 3] = tf32r(a.w * b.w);
        }
    }
    __syncthreads();
    float acc[16][4];
#pragma unroll
    for (int i = 0; i < 16; i++)
#pragma unroll
        for (int q = 0; q < 4; q++) acc[i][q] = 0.f;
    gemm_tile(As, Bs, wr, wc, lane, acc);

    int r = lane >> 2, c = lane & 3;
#pragma unroll
    for (int mi = 0; mi < 2; mi++)
#pragma unroll
        for (int h = 0; h < 2; h++) {
            int row = wr * 32 + mi * 16 + r + h * 8;
            int sn = ssrc[row], dn = sdst_[row];
            float p = 0.f;
#pragma unroll
            for (int ni = 0; ni < 8; ni++) {
                int col = wc * 64 + ni * 8 + 2 * c;
                float2 s2 = *(const float2*)(g_S + (size_t)sn * D + col);
                float2 d2 = *(const float2*)(g_Dt + (size_t)dn * D + col);
                float v0 = acc[mi * 8 + ni][h * 2 + 0] + s2.x + d2.x + sbias[col];
                float v1 = acc[mi * 8 + ni][h * 2 + 1] + s2.y + d2.y + sbias[col + 1];
                p = fmaf(gelu_f(v0), sw[col], p);
                p = fmaf(gelu_f(v1), sw[col + 1], p);
            }
            red[row * 8 + wc * 4 + c] = p;
        }
    __syncthreads();
    if (t < 128) {
        float s = 0.f;
#pragma unroll
        for (int x = 0; x < 8; x++) s += red[t * 8 + x];
        s += baout[0];
        s = (s > 0.f) ? s : 0.2f * s;
        g_score[p0 + t] = s;
    }
}

// ---------------- stage 3: aggregation (warp per node) ----------------
__global__ void agg_kernel() {
    int gw = (blockIdx.x * blockDim.x + threadIdx.x) >> 5;
    int lane = threadIdx.x & 31;
    if (gw >= NN) return;
    int beg = g_rowptr[gw], end = g_rowptr[gw + 1];
    int off = lane * 4;
    float4 mx = make_float4(-FLT_MAX, -FLT_MAX, -FLT_MAX, -FLT_MAX);
    float4 sum = make_float4(0.f, 0.f, 0.f, 0.f);
    for (int p = beg; p < end; p++) {
        float sc = g_score[p];
        int sn = g_sbuf[p];
        float4 h = *(const float4*)&g_H[(size_t)sn * D + off];
        float4 h2 = *(const float4*)&g_H2[(size_t)sn * D + off];
        mx.x = fmaxf(mx.x, sc * h.x); mx.y = fmaxf(mx.y, sc * h.y);
        mx.z = fmaxf(mx.z, sc * h.z); mx.w = fmaxf(mx.w, sc * h.w);
        sum.x = fmaf(sc, h2.x, sum.x); sum.y = fmaf(sc, h2.y, sum.y);
        sum.z = fmaf(sc, h2.z, sum.z); sum.w = fmaf(sc, h2.w, sum.w);
    }
    int d = end - beg;
    if (d == 0) mx = make_float4(0.f, 0.f, 0.f, 0.f);
    float inv = 1.f / (float)(d > 1 ? d : 1);
    sum.x *= inv; sum.y *= inv; sum.z *= inv; sum.w *= inv;
    *(float4*)&g_neigh[(size_t)gw * D + off] = mx;
    *(float4*)&g_neigh2[(size_t)gw * D + off] = sum;
}

// ---------------- stage 4: output GEMMs + fused MLP ----------------
__global__ __launch_bounds__(256, 1) void final_mma(const float* __restrict__ feat,
                                                    const float* __restrict__ Wself,
                                                    const float* __restrict__ bself,
                                                    const float* __restrict__ Wneigh,
                                                    const float* __restrict__ bneigh,
                                                    const float* __restrict__ Wneigh2,
                                                    const float* __restrict__ bneigh2,
                                                    const float* __restrict__ Wmlp,
                                                    const float* __restrict__ bmlp,
                                                    float* __restrict__ out) {
    extern __shared__ float sm[];
    float* As = sm;
    float* Bs = sm + D * PITCH;
    __shared__ float sbias[D], sb2[D];
    int t = threadIdx.x, lane = t & 31, warp = t >> 5;
    int wr = warp >> 1, wc = warp & 1;
    int base = blockIdx.x * 128;
    int r = lane >> 2, c = lane & 3;

    if (t < D) sbias[t] = bself[t] + bneigh[t] + bneigh2[t];
    float acc[16][4];
#pragma unroll
    for (int i = 0; i < 16; i++)
#pragma unroll
        for (int q = 0; q < 4; q++) acc[i][q] = 0.f;

    for (int s3 = 0; s3 < 3; s3++) {
        const float* X = s3 == 0 ? feat : s3 == 1 ? g_neigh : g_neigh2;
        const float* W = s3 == 0 ? Wself : s3 == 1 ? Wneigh : Wneigh2;
        __syncthreads();
        {
            int row = t >> 1, k0 = (t & 1) * 64;
            int node = base + row;
            float* ap = As + row * PITCH + k0;
            if (node < NN) {
                const float* fr = X + (size_t)node * D + k0;
#pragma unroll
                for (int k = 0; k < 64; k += 4) {
                    float4 v = *(const float4*)(fr + k);
                    ap[k] = tf32r(v.x); ap[k + 1] = tf32r(v.y);
                    ap[k + 2] = tf32r(v.z); ap[k + 3] = tf32r(v.w);
                }
            } else {
                for (int k = 0; k < 64; k++) ap[k] = 0.f;
            }
        }
        stage_B(Bs, W, t);
        __syncthreads();
        gemm_tile(As, Bs, wr, wc, lane, acc);
    }
#pragma unroll
    for (int mi = 0; mi < 2; mi++)
#pragma unroll
        for (int ni = 0; ni < 8; ni++) {
            int col = wc * 64 + ni * 8 + 2 * c;
            acc[mi * 8 + ni][0] += sbias[col];
            acc[mi * 8 + ni][1] += sbias[col + 1];
            acc[mi * 8 + ni][2] += sbias[col];
            acc[mi * 8 + ni][3] += sbias[col + 1];
        }

    for (int li = 0; li < 2; li++) {
        __syncthreads();
#pragma unroll
        for (int mi = 0; mi < 2; mi++)
#pragma unroll
            for (int h = 0; h < 2; h++) {
                int row = wr * 32 + mi * 16 + r + h * 8;
#pragma unroll
                for (int ni = 0; ni < 8; ni++) {
                    int col = wc * 64 + ni * 8 + 2 * c;
                    As[row * PITCH + col] = tf32r(gelu_f(acc[mi * 8 + ni][h * 2 + 0]));
                    As[row * PITCH + col + 1] = tf32r(gelu_f(acc[mi * 8 + ni][h * 2 + 1]));
                }
            }
        stage_B(Bs, Wmlp + (size_t)li * D * D, t);
        if (t < D) sb2[t] = bmlp[li * D + t];
        __syncthreads();
        float d2[16][4];
#pragma unroll
        for (int i = 0; i < 16; i++)
#pragma unroll
            for (int q = 0; q < 4; q++) d2[i][q] = 0.f;
        gemm_tile(As, Bs, wr, wc, lane, d2);
#pragma unroll
        for (int mi = 0; mi < 2; mi++)
#pragma unroll
            for (int ni = 0; ni < 8; ni++) {
                int col = wc * 64 + ni * 8 + 2 * c;
                acc[mi * 8 + ni][0] += d2[mi * 8 + ni][0] + sb2[col];
                acc[mi * 8 + ni][1] += d2[mi * 8 + ni][1] + sb2[col + 1];
                acc[mi * 8 + ni][2] += d2[mi * 8 + ni][2] + sb2[col];
                acc[mi * 8 + ni][3] += d2[mi * 8 + ni][3] + sb2[col + 1];
            }
    }
#pragma unroll
    for (int mi = 0; mi < 2; mi++)
#pragma unroll
        for (int h = 0; h < 2; h++) {
            int node = base + wr * 32 + mi * 16 + r + h * 8;
            if (node < NN) {
#pragma unroll
                for (int ni = 0; ni < 8; ni++) {
                    int col = wc * 64 + ni * 8 + 2 * c;
                    *(float2*)(out + (size_t)node * D + col) =
                        make_float2(acc[mi * 8 + ni][h * 2 + 0], acc[mi * 8 + ni][h * 2 + 1]);
                }
            }
        }
}

// ---------------- launch ----------------
extern "C" void kernel_launch(void* const* d_in, const int* in_sizes, int n_in,
                              void* d_out, int out_size) {
    const float* feat = (const float*)d_in[0];
    const int* src = (const int*)d_in[1];
    const int* dst = (const int*)d_in[2];
    const float* Wasrc = (const float*)d_in[3];
    const float* basrc = (const float*)d_in[4];
    const float* Wadst = (const float*)d_in[5];
    const float* badst = (const float*)d_in[6];
    const float* Wasub = (const float*)d_in[7];
    const float* basub = (const float*)d_in[8];
    const float* Wamul = (const float*)d_in[9];
    const float* bamul = (const float*)d_in[10];
    const float* Waout = (const float*)d_in[11];
    const float* baout = (const float*)d_in[12];
    const float* Wpool = (const float*)d_in[13];
    const float* bpool = (const float*)d_in[14];
    const float* Wpool2 = (const float*)d_in[15];
    const float* bpool2 = (const float*)d_in[16];
    const float* Wself = (const float*)d_in[17];
    const float* bself = (const float*)d_in[18];
    const float* Wneigh = (const float*)d_in[19];
    const float* bneigh = (const float*)d_in[20];
    const float* Wneigh2 = (const float*)d_in[21];
    const float* bneigh2 = (const float*)d_in[22];
    const float* Wmlp = (const float*)d_in[23];
    const float* bmlp = (const float*)d_in[24];
    float* out = (float*)d_out;

    const int SMEM_GEMM = 2 * D * PITCH * (int)sizeof(float);        // 135168
    const int SMEM_EDGE = SMEM_GEMM + 128 * 8 * (int)sizeof(float);  // 139264
    cudaFuncSetAttribute(node_mma, cudaFuncAttributeMaxDynamicSharedMemorySize, SMEM_GEMM);
    cudaFuncSetAttribute(edge_mma, cudaFuncAttributeMaxDynamicSharedMemorySize, SMEM_EDGE);
    cudaFuncSetAttribute(final_mma, cudaFuncAttributeMaxDynamicSharedMemorySize, SMEM_GEMM);

    prep_kernel<<<64, 256>>>(Wasrc, Wadst, Wasub, basrc, badst, basub, bamul);
    init_deg_kernel<<<(NN + 255) / 256, 256>>>();
    deg_kernel<<<(NE + 255) / 256, 256>>>(dst);
    scan1_kernel<<<NBLK, 256>>>();
    scan2_kernel<<<1, 256>>>();
    scan3_kernel<<<NBLK, 256>>>();
    fill_kernel<<<(NE + 255) / 256, 256>>>(src, dst);
    node_mma<<<(NN + 127) / 128, 256, SMEM_GEMM>>>(feat, Wpool, bpool, Wpool2, bpool2);
    edge_mma<<<NE / 128, 256, SMEM_EDGE>>>(feat, Wamul, Waout, baout);
    agg_kernel<<<(NN * 32 + 255) / 256, 256>>>();
    final_mma<<<(NN + 127) / 128, 256, SMEM_GEMM>>>(feat, Wself, bself, Wneigh, bneigh,
                                                    Wneigh2, bneigh2, Wmlp, bmlp, out);
}